// round 4
// baseline (speedup 1.0000x reference)
#include <cuda_runtime.h>

#define BB 4
#define SS_DIM 1024
#define XX 1024
#define CC 8
#define DD 2
#define WIDTH 16
#define DEPTH 4
#define SCHUNK 32
#define TPB 256

typedef unsigned long long u64;

__device__ __forceinline__ u64 fma2(u64 a, u64 b, u64 c) {
    u64 d;
    asm("fma.rn.f32x2 %0, %1, %2, %3;" : "=l"(d) : "l"(a), "l"(b), "l"(c));
    return d;
}
__device__ __forceinline__ u64 add2(u64 a, u64 b) {
    u64 d;
    asm("add.rn.f32x2 %0, %1, %2;" : "=l"(d) : "l"(a), "l"(b));
    return d;
}
__device__ __forceinline__ u64 dup2(float a) {
    u64 r; unsigned ai = __float_as_uint(a);
    asm("mov.b64 %0, {%1, %1};" : "=l"(r) : "r"(ai));
    return r;
}
__device__ __forceinline__ u64 pack2(float a, float b) {
    u64 r;
    asm("mov.b64 %0, {%1, %2};" : "=l"(r) : "f"(a), "f"(b));
    return r;
}
__device__ __forceinline__ void unpack2(u64 v, float& a, float& b) {
    unsigned x, y;
    asm("mov.b64 {%0, %1}, %2;" : "=r"(x), "=r"(y) : "l"(v));
    a = __uint_as_float(x);
    b = __uint_as_float(y);
}
__device__ __forceinline__ float fast_tanh(float x) {
    float y;
    asm("tanh.approx.f32 %0, %1;" : "=f"(y) : "f"(x));
    return y;
}

// One residual layer for 2 points, j-dimension split into halves to cap
// live registers (z is 8 u64 per half instead of 16).
__device__ __forceinline__ void res_layer(const u64 (*sW)[WIDTH / 2],
                                          const u64* sb,
                                          const u64 hi0[WIDTH / 2],
                                          const u64 hi1[WIDTH / 2],
                                          u64 ho0[WIDTH / 2],
                                          u64 ho1[WIDTH / 2]) {
#pragma unroll
    for (int jh = 0; jh < 2; ++jh) {
        u64 z0[4], z1[4];
#pragma unroll
        for (int jp = 0; jp < 4; ++jp) {
            const u64 bi = sb[jh * 4 + jp];
            z0[jp] = bi;
            z1[jp] = bi;
        }
#pragma unroll
        for (int kp = 0; kp < WIDTH / 2; ++kp) {
            float a0, b0, a1, b1;
            unpack2(hi0[kp], a0, b0);
            unpack2(hi1[kp], a1, b1);
            const u64 d0a = dup2(a0), d0b = dup2(b0);
            const u64 d1a = dup2(a1), d1b = dup2(b1);
#pragma unroll
            for (int jp = 0; jp < 4; ++jp) {
                const u64 wa = sW[2 * kp][jh * 4 + jp];
                const u64 wb = sW[2 * kp + 1][jh * 4 + jp];
                z0[jp] = fma2(d0a, wa, z0[jp]);
                z1[jp] = fma2(d1a, wa, z1[jp]);
                z0[jp] = fma2(d0b, wb, z0[jp]);
                z1[jp] = fma2(d1b, wb, z1[jp]);
            }
        }
#pragma unroll
        for (int jp = 0; jp < 4; ++jp) {
            float za, zb;
            unpack2(z0[jp], za, zb);
            ho0[jh * 4 + jp] = add2(hi0[jh * 4 + jp], pack2(fast_tanh(za), fast_tanh(zb)));
            unpack2(z1[jp], za, zb);
            ho1[jh * 4 + jp] = add2(hi1[jh * 4 + jp], pack2(fast_tanh(za), fast_tanh(zb)));
        }
    }
}

__global__ __launch_bounds__(TPB, 1)
void ccl_kernel(const float* __restrict__ yu,
                const float* __restrict__ xin,
                const float* __restrict__ gWin,
                const float* __restrict__ gbin,
                const float* __restrict__ gWhid,
                const float* __restrict__ gbhid,
                const float* __restrict__ gWout,
                const float* __restrict__ gbout,
                float* __restrict__ out) {
    __shared__ u64 s_Whid[DEPTH][WIDTH][WIDTH / 2];  // 4KB
    __shared__ u64 s_bhid[DEPTH][WIDTH / 2];
    __shared__ u64 s_Win[WIDTH / 2];
    __shared__ u64 s_bin[WIDTH / 2];
    __shared__ u64 s_Wout[WIDTH / 2];
    __shared__ float s_bout;
    __shared__ u64 s_y[SCHUNK];
    __shared__ u64 s_u[SCHUNK][CC / 2];

    const int t  = threadIdx.x;
    const int b  = blockIdx.z;
    const int s0 = blockIdx.y * SCHUNK;
    const int xi = blockIdx.x * TPB + t;

    {
        const u64* gW = (const u64*)gWhid;  // 512 u64
        for (int i = t; i < DEPTH * WIDTH * WIDTH / 2; i += TPB)
            ((u64*)s_Whid)[i] = gW[i];
        if (t < DEPTH * WIDTH / 2) ((u64*)s_bhid)[t] = ((const u64*)gbhid)[t];
        if (t < WIDTH / 2) {
            s_Win[t]  = ((const u64*)gWin)[t];
            s_bin[t]  = ((const u64*)gbin)[t];
            s_Wout[t] = ((const u64*)gWout)[t];
        }
        if (t == 0) s_bout = gbout[0];
        for (int i = t; i < SCHUNK * 5; i += TPB) {
            const int s = i / 5, q = i % 5;
            const u64* row = (const u64*)(yu + ((size_t)b * SS_DIM + (s0 + s)) * (CC + DD));
            if (q < 4) s_u[s][q] = row[q];
            else       s_y[s]    = row[4];
        }
    }
    __syncthreads();

    const float2 xv = *reinterpret_cast<const float2*>(&xin[((size_t)b * XX + xi) * DD]);

    u64 acc2[CC / 2];
#pragma unroll
    for (int cp = 0; cp < CC / 2; ++cp) acc2[cp] = 0ull;

#pragma unroll 1
    for (int ss0 = 0; ss0 < SCHUNK; ss0 += 2) {
        u64 hA0[WIDTH / 2], hA1[WIDTH / 2];
        u64 hB0[WIDTH / 2], hB1[WIDTH / 2];
        {
            float ya, yb;
            unpack2(s_y[ss0 + 0], ya, yb);
            float d0 = xv.x - ya, d1 = xv.y - yb;
            const u64 r0 = dup2(fmaf(d1, d1, d0 * d0));
            unpack2(s_y[ss0 + 1], ya, yb);
            d0 = xv.x - ya; d1 = xv.y - yb;
            const u64 r1 = dup2(fmaf(d1, d1, d0 * d0));
#pragma unroll
            for (int jp = 0; jp < WIDTH / 2; ++jp) {
                const u64 w = s_Win[jp], bi = s_bin[jp];
                hA0[jp] = fma2(r0, w, bi);
                hA1[jp] = fma2(r1, w, bi);
            }
        }

        // 4 layers, ping-pong hA <-> hB
        res_layer(s_Whid[0], s_bhid[0], hA0, hA1, hB0, hB1);
        res_layer(s_Whid[1], s_bhid[1], hB0, hB1, hA0, hA1);
        res_layer(s_Whid[2], s_bhid[2], hA0, hA1, hB0, hB1);
        res_layer(s_Whid[3], s_bhid[3], hB0, hB1, hA0, hA1);

        {
            u64 k0 = 0ull, k1 = 0ull;
#pragma unroll
            for (int jp = 0; jp < WIDTH / 2; ++jp) {
                const u64 w = s_Wout[jp];
                k0 = fma2(hA0[jp], w, k0);
                k1 = fma2(hA1[jp], w, k1);
            }
            float ka, kb;
            unpack2(k0, ka, kb);
            const u64 kd0 = dup2(ka + kb + s_bout);
            unpack2(k1, ka, kb);
            const u64 kd1 = dup2(ka + kb + s_bout);
#pragma unroll
            for (int cp = 0; cp < CC / 2; ++cp) {
                acc2[cp] = fma2(kd0, s_u[ss0 + 0][cp], acc2[cp]);
                acc2[cp] = fma2(kd1, s_u[ss0 + 1][cp], acc2[cp]);
            }
        }
    }

    const float invS = 1.0f / (float)SS_DIM;
    float* op = &out[((size_t)b * XX + xi) * CC];
#pragma unroll
    for (int cp = 0; cp < CC / 2; ++cp) {
        float a0, a1;
        unpack2(acc2[cp], a0, a1);
        atomicAdd(&op[2 * cp],     a0 * invS);
        atomicAdd(&op[2 * cp + 1], a1 * invS);
    }
}

extern "C" void kernel_launch(void* const* d_in, const int* in_sizes, int n_in,
                              void* d_out, int out_size) {
    const float* yu    = (const float*)d_in[0]; // (4,1024,10)
    const float* x     = (const float*)d_in[1]; // (4,1024,2)
    const float* W_in  = (const float*)d_in[2]; // (1,16)
    const float* b_in  = (const float*)d_in[3]; // (16,)
    const float* W_hid = (const float*)d_in[4]; // (4,16,16)
    const float* b_hid = (const float*)d_in[5]; // (4,16)
    const float* W_out = (const float*)d_in[6]; // (16,1)
    const float* b_out = (const float*)d_in[7]; // (1,)

    (void)in_sizes; (void)n_in;

    cudaMemsetAsync(d_out, 0, (size_t)out_size * sizeof(float), 0);

    dim3 grid(XX / TPB, SS_DIM / SCHUNK, BB);
    ccl_kernel<<<grid, TPB, 0, 0>>>(yu, x, W_in, b_in, W_hid, b_hid, W_out, b_out,
                                    (float*)d_out);
}

// round 5
// speedup vs baseline: 9.4885x; 9.4885x over previous
#include <cuda_runtime.h>

#define BB 4
#define SS_DIM 1024
#define XX 1024
#define CC 8
#define DD 2
#define WIDTH 16
#define DEPTH 4
#define SCHUNK 32
#define TPB 128

__constant__ float c_Win[WIDTH];
__constant__ float c_bin[WIDTH];
__constant__ float c_Whid[DEPTH][WIDTH][WIDTH];
__constant__ float c_bhid[DEPTH][WIDTH];
__constant__ float c_Wout[WIDTH];
__constant__ float c_bout[1];

__device__ __forceinline__ float fast_tanh(float x) {
    float y;
    asm("tanh.approx.f32 %0, %1;" : "=f"(y) : "f"(x));
    return y;
}

__global__ __launch_bounds__(TPB, 4)
void ccl_kernel(const float* __restrict__ yu,
                const float* __restrict__ xin,
                float* __restrict__ out) {
    __shared__ float s_y[SCHUNK][DD];
    __shared__ float s_u[SCHUNK][CC];

    const int t  = threadIdx.x;
    const int b  = blockIdx.z;
    const int s0 = blockIdx.y * SCHUNK;
    const int xi = blockIdx.x * TPB + t;

    // Stage this block's yu chunk: 32 rows x 10 floats.
    for (int i = t; i < SCHUNK * (CC + DD); i += TPB) {
        const int s = i / (CC + DD);
        const int c = i % (CC + DD);
        const float v = yu[((size_t)b * SS_DIM + (s0 + s)) * (CC + DD) + c];
        if (c < CC) s_u[s][c] = v;
        else        s_y[s][c - CC] = v;
    }
    __syncthreads();

    const float2 xv = *reinterpret_cast<const float2*>(&xin[((size_t)b * XX + xi) * DD]);

    float acc[CC];
#pragma unroll
    for (int c = 0; c < CC; ++c) acc[c] = 0.0f;

#pragma unroll 1
    for (int ss0 = 0; ss0 < SCHUNK; ss0 += 2) {
        // r for both points
        float d0 = xv.x - s_y[ss0][0];
        float d1 = xv.y - s_y[ss0][1];
        const float r0 = fmaf(d1, d1, d0 * d0);
        d0 = xv.x - s_y[ss0 + 1][0];
        d1 = xv.y - s_y[ss0 + 1][1];
        const float r1 = fmaf(d1, d1, d0 * d0);

        float h0[WIDTH], h1[WIDTH];
#pragma unroll
        for (int j = 0; j < WIDTH; ++j) {
            const float w = c_Win[j], bi = c_bin[j];
            h0[j] = fmaf(r0, w, bi);
            h1[j] = fmaf(r1, w, bi);
        }

#pragma unroll
        for (int l = 0; l < DEPTH; ++l) {
            float z0[WIDTH], z1[WIDTH];
#pragma unroll
            for (int j = 0; j < WIDTH; ++j) {
                const float bi = c_bhid[l][j];
                z0[j] = bi;
                z1[j] = bi;
            }
#pragma unroll
            for (int kk = 0; kk < WIDTH; ++kk) {
                const float a0 = h0[kk];
                const float a1 = h1[kk];
#pragma unroll
                for (int j = 0; j < WIDTH; ++j) {
                    const float w = c_Whid[l][kk][j];   // uniform load, shared by both points
                    z0[j] = fmaf(a0, w, z0[j]);
                    z1[j] = fmaf(a1, w, z1[j]);
                }
            }
#pragma unroll
            for (int j = 0; j < WIDTH; ++j) {
                h0[j] += fast_tanh(z0[j]);
                h1[j] += fast_tanh(z1[j]);
            }
        }

        float k0 = c_bout[0], k1 = c_bout[0];
#pragma unroll
        for (int j = 0; j < WIDTH; ++j) {
            const float w = c_Wout[j];
            k0 = fmaf(h0[j], w, k0);
            k1 = fmaf(h1[j], w, k1);
        }

#pragma unroll
        for (int c = 0; c < CC; ++c) {
            acc[c] = fmaf(k0, s_u[ss0][c], acc[c]);
            acc[c] = fmaf(k1, s_u[ss0 + 1][c], acc[c]);
        }
    }

    const float invS = 1.0f / (float)SS_DIM;
    float* op = &out[((size_t)b * XX + xi) * CC];
#pragma unroll
    for (int c = 0; c < CC; ++c) atomicAdd(&op[c], acc[c] * invS);
}

extern "C" void kernel_launch(void* const* d_in, const int* in_sizes, int n_in,
                              void* d_out, int out_size) {
    const float* yu    = (const float*)d_in[0]; // (4,1024,10)
    const float* x     = (const float*)d_in[1]; // (4,1024,2)
    const float* W_in  = (const float*)d_in[2]; // (1,16)
    const float* b_in  = (const float*)d_in[3]; // (16,)
    const float* W_hid = (const float*)d_in[4]; // (4,16,16)
    const float* b_hid = (const float*)d_in[5]; // (4,16)
    const float* W_out = (const float*)d_in[6]; // (16,1)
    const float* b_out = (const float*)d_in[7]; // (1,)

    (void)in_sizes; (void)n_in;

    cudaMemcpyToSymbolAsync(c_Win,  W_in,  WIDTH * sizeof(float), 0, cudaMemcpyDeviceToDevice, 0);
    cudaMemcpyToSymbolAsync(c_bin,  b_in,  WIDTH * sizeof(float), 0, cudaMemcpyDeviceToDevice, 0);
    cudaMemcpyToSymbolAsync(c_Whid, W_hid, DEPTH * WIDTH * WIDTH * sizeof(float), 0, cudaMemcpyDeviceToDevice, 0);
    cudaMemcpyToSymbolAsync(c_bhid, b_hid, DEPTH * WIDTH * sizeof(float), 0, cudaMemcpyDeviceToDevice, 0);
    cudaMemcpyToSymbolAsync(c_Wout, W_out, WIDTH * sizeof(float), 0, cudaMemcpyDeviceToDevice, 0);
    cudaMemcpyToSymbolAsync(c_bout, b_out, 1 * sizeof(float), 0, cudaMemcpyDeviceToDevice, 0);

    cudaMemsetAsync(d_out, 0, (size_t)out_size * sizeof(float), 0);

    dim3 grid(XX / TPB, SS_DIM / SCHUNK, BB);
    ccl_kernel<<<grid, TPB, 0, 0>>>(yu, x, (float*)d_out);
}

// round 6
// speedup vs baseline: 9.7506x; 1.0276x over previous
#include <cuda_runtime.h>

#define BB 4
#define SS_DIM 1024
#define XX 1024
#define CC 8
#define DD 2
#define WIDTH 16
#define DEPTH 4
#define SCHUNK 32
#define TPB 128
#define PP 4

__constant__ float c_Win[WIDTH];
__constant__ float c_bin[WIDTH];
__constant__ float c_Whid[DEPTH][WIDTH][WIDTH];
__constant__ float c_bhid[DEPTH][WIDTH];
__constant__ float c_Wout[WIDTH];
__constant__ float c_bout[1];

__device__ __forceinline__ float fast_tanh(float x) {
    float y;
    asm("tanh.approx.f32 %0, %1;" : "=f"(y) : "f"(x));
    return y;
}

__global__ __launch_bounds__(TPB, 2)
void ccl_kernel(const float* __restrict__ yu,
                const float* __restrict__ xin,
                float* __restrict__ out) {
    __shared__ float s_y[SCHUNK][DD];
    __shared__ float s_u[SCHUNK][CC];

    const int t  = threadIdx.x;
    const int b  = blockIdx.z;
    const int s0 = blockIdx.y * SCHUNK;
    const int xi = blockIdx.x * TPB + t;

    for (int i = t; i < SCHUNK * (CC + DD); i += TPB) {
        const int s = i / (CC + DD);
        const int c = i % (CC + DD);
        const float v = yu[((size_t)b * SS_DIM + (s0 + s)) * (CC + DD) + c];
        if (c < CC) s_u[s][c] = v;
        else        s_y[s][c - CC] = v;
    }
    __syncthreads();

    const float2 xv = *reinterpret_cast<const float2*>(&xin[((size_t)b * XX + xi) * DD]);

    float acc[CC];
#pragma unroll
    for (int c = 0; c < CC; ++c) acc[c] = 0.0f;

#pragma unroll 1
    for (int ss0 = 0; ss0 < SCHUNK; ss0 += PP) {
        float h[PP][WIDTH];
        {
            float r[PP];
#pragma unroll
            for (int p = 0; p < PP; ++p) {
                const float d0 = xv.x - s_y[ss0 + p][0];
                const float d1 = xv.y - s_y[ss0 + p][1];
                r[p] = fmaf(d1, d1, d0 * d0);
            }
#pragma unroll
            for (int jq = 0; jq < WIDTH / 4; ++jq) {
                const float4 w  = reinterpret_cast<const float4*>(c_Win)[jq];
                const float4 bi = reinterpret_cast<const float4*>(c_bin)[jq];
#pragma unroll
                for (int p = 0; p < PP; ++p) {
                    h[p][4 * jq + 0] = fmaf(r[p], w.x, bi.x);
                    h[p][4 * jq + 1] = fmaf(r[p], w.y, bi.y);
                    h[p][4 * jq + 2] = fmaf(r[p], w.z, bi.z);
                    h[p][4 * jq + 3] = fmaf(r[p], w.w, bi.w);
                }
            }
        }

#pragma unroll
        for (int l = 0; l < DEPTH; ++l) {
            float z[PP][WIDTH];
#pragma unroll
            for (int jq = 0; jq < WIDTH / 4; ++jq) {
                const float4 bi = reinterpret_cast<const float4*>(c_bhid[l])[jq];
#pragma unroll
                for (int p = 0; p < PP; ++p) {
                    z[p][4 * jq + 0] = bi.x;
                    z[p][4 * jq + 1] = bi.y;
                    z[p][4 * jq + 2] = bi.z;
                    z[p][4 * jq + 3] = bi.w;
                }
            }
#pragma unroll
            for (int kk = 0; kk < WIDTH; ++kk) {
#pragma unroll
                for (int jq = 0; jq < WIDTH / 4; ++jq) {
                    const float4 w = reinterpret_cast<const float4*>(c_Whid[l][kk])[jq];
#pragma unroll
                    for (int p = 0; p < PP; ++p) {
                        const float a = h[p][kk];
                        z[p][4 * jq + 0] = fmaf(a, w.x, z[p][4 * jq + 0]);
                        z[p][4 * jq + 1] = fmaf(a, w.y, z[p][4 * jq + 1]);
                        z[p][4 * jq + 2] = fmaf(a, w.z, z[p][4 * jq + 2]);
                        z[p][4 * jq + 3] = fmaf(a, w.w, z[p][4 * jq + 3]);
                    }
                }
            }
#pragma unroll
            for (int p = 0; p < PP; ++p)
#pragma unroll
                for (int j = 0; j < WIDTH; ++j)
                    h[p][j] += fast_tanh(z[p][j]);
        }

        float k[PP];
#pragma unroll
        for (int p = 0; p < PP; ++p) k[p] = c_bout[0];
#pragma unroll
        for (int jq = 0; jq < WIDTH / 4; ++jq) {
            const float4 w = reinterpret_cast<const float4*>(c_Wout)[jq];
#pragma unroll
            for (int p = 0; p < PP; ++p) {
                k[p] = fmaf(h[p][4 * jq + 0], w.x, k[p]);
                k[p] = fmaf(h[p][4 * jq + 1], w.y, k[p]);
                k[p] = fmaf(h[p][4 * jq + 2], w.z, k[p]);
                k[p] = fmaf(h[p][4 * jq + 3], w.w, k[p]);
            }
        }

#pragma unroll
        for (int p = 0; p < PP; ++p)
#pragma unroll
            for (int c = 0; c < CC; ++c)
                acc[c] = fmaf(k[p], s_u[ss0 + p][c], acc[c]);
    }

    const float invS = 1.0f / (float)SS_DIM;
    float* op = &out[((size_t)b * XX + xi) * CC];
#pragma unroll
    for (int c = 0; c < CC; ++c) atomicAdd(&op[c], acc[c] * invS);
}

extern "C" void kernel_launch(void* const* d_in, const int* in_sizes, int n_in,
                              void* d_out, int out_size) {
    const float* yu    = (const float*)d_in[0]; // (4,1024,10)
    const float* x     = (const float*)d_in[1]; // (4,1024,2)
    const float* W_in  = (const float*)d_in[2]; // (1,16)
    const float* b_in  = (const float*)d_in[3]; // (16,)
    const float* W_hid = (const float*)d_in[4]; // (4,16,16)
    const float* b_hid = (const float*)d_in[5]; // (4,16)
    const float* W_out = (const float*)d_in[6]; // (16,1)
    const float* b_out = (const float*)d_in[7]; // (1,)

    (void)in_sizes; (void)n_in;

    cudaMemcpyToSymbolAsync(c_Win,  W_in,  WIDTH * sizeof(float), 0, cudaMemcpyDeviceToDevice, 0);
    cudaMemcpyToSymbolAsync(c_bin,  b_in,  WIDTH * sizeof(float), 0, cudaMemcpyDeviceToDevice, 0);
    cudaMemcpyToSymbolAsync(c_Whid, W_hid, DEPTH * WIDTH * WIDTH * sizeof(float), 0, cudaMemcpyDeviceToDevice, 0);
    cudaMemcpyToSymbolAsync(c_bhid, b_hid, DEPTH * WIDTH * sizeof(float), 0, cudaMemcpyDeviceToDevice, 0);
    cudaMemcpyToSymbolAsync(c_Wout, W_out, WIDTH * sizeof(float), 0, cudaMemcpyDeviceToDevice, 0);
    cudaMemcpyToSymbolAsync(c_bout, b_out, 1 * sizeof(float), 0, cudaMemcpyDeviceToDevice, 0);

    cudaMemsetAsync(d_out, 0, (size_t)out_size * sizeof(float), 0);

    dim3 grid(XX / TPB, SS_DIM / SCHUNK, BB);
    ccl_kernel<<<grid, TPB, 0, 0>>>(yu, x, (float*)d_out);
}